// round 17
// baseline (speedup 1.0000x reference)
#include <cuda_runtime.h>
#include <cuda_fp16.h>

#define RES 256
#define NA  180
#define NB  4
#define PW  257            // x0p in [0,256]
#define PH  257            // y0p in [0,256]
#define NPIX (PH*PW)
#define NOUT (NB*NA*RES)

// Corner-packed fp16 images, all 4 batches in 32 bytes per padded pixel.
//   a.x = h2(b0.v00,b0.v01)  a.y = h2(b0.v10,b0.v11)
//   a.z = h2(b1.v00,b1.v01)  a.w = h2(b1.v10,b1.v11)
//   b.* = same for batches 2,3.
// vXY = img[y0+X][x0+Y], OOB -> 0 (zero border = reference's validity mask).
struct __align__(32) Px { uint4 a, b; };
__device__ Px g_P[NPIX];

__device__ __forceinline__ unsigned pack2(float a, float b) {
    __half2 h = __floats2half2_rn(a, b);
    return *reinterpret_cast<unsigned*>(&h);
}
__device__ __forceinline__ float2 unpack2(unsigned u) {
    __half2 h = *reinterpret_cast<__half2*>(&u);
    return __half22float2(h);
}

// 256-bit global load (sm_100+).
__device__ __forceinline__ void ldg256(const Px* p, uint4& a, uint4& b) {
    asm volatile("ld.global.nc.v8.u32 {%0,%1,%2,%3,%4,%5,%6,%7}, [%8];"
                 : "=r"(a.x), "=r"(a.y), "=r"(a.z), "=r"(a.w),
                   "=r"(b.x), "=r"(b.y), "=r"(b.z), "=r"(b.w)
                 : "l"(p));
}
// Register barrier: ties a load's output regs in place so its consumption
// cannot be scheduled before the barrier point.
__device__ __forceinline__ void regbar(uint4& a, uint4& b) {
    asm volatile("" : "+r"(a.x), "+r"(a.y), "+r"(a.z), "+r"(a.w),
                      "+r"(b.x), "+r"(b.y), "+r"(b.z), "+r"(b.w));
}

// Prep: one thread per (pixel, batch): 4 scalar loads, one coalesced 8B store.
// Thread t -> pixel idx = t>>2, batch b = t&3; stores the b-th uint2 of Px.
// Output zeroing folded in (NPIX*NB = 264K threads >= NOUT = 184K).
__global__ __launch_bounds__(256) void prep_kernel(const float* __restrict__ imgs,
                                                   float* __restrict__ out)
{
    int t = blockIdx.x * blockDim.x + threadIdx.x;
    if (t < NOUT) out[t] = 0.0f;
    if (t >= NPIX * NB) return;
    const int b   = t & 3;
    const int idx = t >> 2;
    const int xp = idx % PW;
    const int yp = idx / PW;
    const int yt = yp - 1, yb = yp;
    const int xl = xp - 1, xr = xp;

    const float* im = imgs + (size_t)b * RES * RES;
    const bool vt = ((unsigned)yt < RES), vb = ((unsigned)yb < RES);
    const bool vl = ((unsigned)xl < RES), vr = ((unsigned)xr < RES);
    const float v00 = (vt && vl) ? __ldg(im + yt * RES + xl) : 0.0f;
    const float v01 = (vt && vr) ? __ldg(im + yt * RES + xr) : 0.0f;
    const float v10 = (vb && vl) ? __ldg(im + yb * RES + xl) : 0.0f;
    const float v11 = (vb && vr) ? __ldg(im + yb * RES + xr) : 0.0f;

    uint2 w;
    w.x = pack2(v00, v01);
    w.y = pack2(v10, v11);
    reinterpret_cast<uint2*>(&g_P[idx])[b] = w;
}

// fp32 bilerp from packed (v00,v01)/(v10,v11) words.
__device__ __forceinline__ void bilerp_acc(unsigned top, unsigned bot,
                                           float wx, float wy, float& acc)
{
    const float2 T = unpack2(top);
    const float2 B = unpack2(bot);
    const float ft = fmaf(wx, T.y - T.x, T.x);
    const float fb = fmaf(wx, B.y - B.x, B.x);
    acc += fmaf(wy, fb - ft, ft);
}

// Block = 128 threads (4 warps). Warp tile: 8 rays x 4 t-phases.
// Grid: (angle, ray_group 0..7, t_half 0..1).
// Each block: 32 rays x 128 t-steps (t = th*128 + 4*i + t4, i in [0,32)).
// Inner loop chunked by 4; all 4 LDG.256 issue before any consume (regbar wall).
__global__ __launch_bounds__(128, 6) void radon_kernel(
    const float* __restrict__ angles,
    const float* __restrict__ rays,
    float* __restrict__ out)
{
    const int tid  = threadIdx.x;
    const int lane = tid & 31;
    const int warp = tid >> 5;        // 0..3
    const int r8   = lane & 7;        // ray within warp tile
    const int t4   = lane >> 3;       // t-phase 0..3
    const int a    = blockIdx.x;      // angle
    const int rg   = blockIdx.y;      // ray group 0..7
    const int th   = blockIdx.z;      // t half 0..1
    const int ray  = rg * 32 + warp * 8 + r8;

    const float4 r4 = __ldg(reinterpret_cast<const float4*>(rays) + ray);
    float s, c;
    sincosf(__ldg(angles + a), &s, &c);

    const float rsx = r4.x * c - r4.y * s;
    const float rsy = r4.x * s + r4.y * c;
    const float dx  = (r4.z * c - r4.w * s) - rsx;
    const float dy  = (r4.z * s + r4.w * c) - rsy;

    const float inv_n = 1.0f / RES;
    const float t0 = (float)(th * 128 + t4) + 0.5f;
    // +128.5 folds image-center offset (127.5) and the +1 padding shift.
    float gx = rsx + 128.5f + dx * inv_n * t0;
    float gy = rsy + 128.5f + dy * inv_n * t0;
    const float sx4 = dx * inv_n * 4.0f;
    const float sy4 = dy * inv_n * 4.0f;

    float acc0 = 0.f, acc1 = 0.f, acc2 = 0.f, acc3 = 0.f;

    for (int i = 0; i < 8; ++i) {
        float wxr[4], wyr[4];
        uint4 qa0, qb0, qa1, qb1, qa2, qb2, qa3, qb3;

        // Addresses for all 4 samples.
        int idxr[4];
        #pragma unroll
        for (int j = 0; j < 4; ++j) {
            const float fx = gx + sx4 * (float)j;
            const float fy = gy + sy4 * (float)j;
            const int x0 = __float2int_rd(fx);
            const int y0 = __float2int_rd(fy);
            wxr[j] = fx - (float)x0;
            wyr[j] = fy - (float)y0;
            idxr[j] = y0 * PW + x0;
        }

        // 4 back-to-back 256-bit loads, then a barrier wall so no consume
        // can be scheduled between them -> MLP = 4.
        ldg256(g_P + idxr[0], qa0, qb0);
        ldg256(g_P + idxr[1], qa1, qb1);
        ldg256(g_P + idxr[2], qa2, qb2);
        ldg256(g_P + idxr[3], qa3, qb3);
        regbar(qa0, qb0);
        regbar(qa1, qb1);
        regbar(qa2, qb2);

        // Consume.
        bilerp_acc(qa0.x, qa0.y, wxr[0], wyr[0], acc0);
        bilerp_acc(qa0.z, qa0.w, wxr[0], wyr[0], acc1);
        bilerp_acc(qb0.x, qb0.y, wxr[0], wyr[0], acc2);
        bilerp_acc(qb0.z, qb0.w, wxr[0], wyr[0], acc3);

        bilerp_acc(qa1.x, qa1.y, wxr[1], wyr[1], acc0);
        bilerp_acc(qa1.z, qa1.w, wxr[1], wyr[1], acc1);
        bilerp_acc(qb1.x, qb1.y, wxr[1], wyr[1], acc2);
        bilerp_acc(qb1.z, qb1.w, wxr[1], wyr[1], acc3);

        bilerp_acc(qa2.x, qa2.y, wxr[2], wyr[2], acc0);
        bilerp_acc(qa2.z, qa2.w, wxr[2], wyr[2], acc1);
        bilerp_acc(qb2.x, qb2.y, wxr[2], wyr[2], acc2);
        bilerp_acc(qb2.z, qb2.w, wxr[2], wyr[2], acc3);

        bilerp_acc(qa3.x, qa3.y, wxr[3], wyr[3], acc0);
        bilerp_acc(qa3.z, qa3.w, wxr[3], wyr[3], acc1);
        bilerp_acc(qb3.x, qb3.y, wxr[3], wyr[3], acc2);
        bilerp_acc(qb3.z, qb3.w, wxr[3], wyr[3], acc3);

        gx += sx4 * 4.0f;
        gy += sy4 * 4.0f;
    }

    // Reduce the 4 t-phases of each ray (lanes l, l+8, l+16, l+24).
    acc0 += __shfl_xor_sync(0xFFFFFFFFu, acc0, 8);
    acc0 += __shfl_xor_sync(0xFFFFFFFFu, acc0, 16);
    acc1 += __shfl_xor_sync(0xFFFFFFFFu, acc1, 8);
    acc1 += __shfl_xor_sync(0xFFFFFFFFu, acc1, 16);
    acc2 += __shfl_xor_sync(0xFFFFFFFFu, acc2, 8);
    acc2 += __shfl_xor_sync(0xFFFFFFFFu, acc2, 16);
    acc3 += __shfl_xor_sync(0xFFFFFFFFu, acc3, 8);
    acc3 += __shfl_xor_sync(0xFFFFFFFFu, acc3, 16);

    if (t4 == 0) {
        const float step = (r4.w - r4.y) * inv_n;   // L / n_steps
        const int base = a * RES + ray;
        atomicAdd(out + 0 * NA * RES + base, acc0 * step);
        atomicAdd(out + 1 * NA * RES + base, acc1 * step);
        atomicAdd(out + 2 * NA * RES + base, acc2 * step);
        atomicAdd(out + 3 * NA * RES + base, acc3 * step);
    }
}

extern "C" void kernel_launch(void* const* d_in, const int* in_sizes, int n_in,
                              void* d_out, int out_size)
{
    const float* imgs   = (const float*)d_in[0];   // [4,256,256]
    const float* angles = (const float*)d_in[1];   // [180]
    const float* rays   = (const float*)d_in[2];   // [256,4]
    float* out          = (float*)d_out;           // [4,180,256]

    prep_kernel<<<(NPIX * NB + 255) / 256, 256>>>(imgs, out);

    dim3 grid(NA, 8, 2);
    radon_kernel<<<grid, 128>>>(angles, rays, out);
}